// round 8
// baseline (speedup 1.0000x reference)
#include <cuda_runtime.h>
#include <cuda_bf16.h>

// ---------------- constants ----------------
#define T_LEN (1 << 21)          // 2,097,152
#define B_CH  8192               // chains (256 steps each)
#define NG    256                // chain groups of 32 (one warp each)
#define S_EQ  166.0f             // stationary-state init for relaxation

// ---------------- device scratch ----------------
__device__ float g_d[T_LEN + 2048];      // transposed d = P - E; padded for prefetch overrun
__device__ float g_send0[B_CH];          // sweep-1 end states
__device__ float g_ck[4][B_CH];          // 64-step checkpoints from stats sweep
__device__ float g_prepart[NG * 4];      // Σpn, Σpn², Σen, Σen² per group
__device__ float g_spart[NG * 4];        // Σps, Σps², Σpc, Σpc² per group
__device__ float g_stats[8];             // mu[4], inv_sigma[4]
__device__ float g_hand[NG];             // sweep-2 end handoff (last chain of group)
__device__ volatile int g_f2[NG];        // handoff flags (zero-init; consumer resets)

// transposed index: idx(C,i) = ((C>>5)<<13) | (i<<5) | (C&31)

// ---------------- forcing -> step operands (bit-identical everywhere) ----------------
__device__ __forceinline__ void make_ops(float d, float& tp350, float& tpn,
                                         float& tn, float& tnn) {
    const float INV = 1.0f / 350.0f;
    float pn  = fmaxf(d, 0.0f);
    float en  = fmaxf(-d, 0.0f);
    float mp  = pn * INV;
    float mp2 = mp * mp;
    float gp  = fmaf(mp2, fmaf(mp2, 0.13333333f, -0.33333333f), 1.0f); // tanh(z)/z
    float me  = en * INV;
    float me2 = me * me;
    float ge  = fmaf(me2, fmaf(me2, 0.13333333f, -0.33333333f), 1.0f);
    tp350 = pn * gp;
    tpn   = (mp * gp) * INV;
    tn    = me * ge;
    tnn   = tn * INV;
}

// ---------------- MUFU-free GR4J step, 40-cycle chain ----------------
// Invariants: tp,tn <= tanh(10/350)=0.02857, 0 <= s < 350.
template <int OUT>
__device__ __forceinline__ float gr_step(float s, float tp350, float tpn,
                                         float tn, float tnn,
                                         float& ps_o, float& pc_o) {
    const float INV = 1.0f / 350.0f;
    constexpr float C49 = 4.0f / (9.0f * 350.0f);
    constexpr float K4  = C49 * C49 * C49 * C49;
    constexpr float A1  = -0.25f * K4;                 // -u/4        (u = K4*v)
    constexpr float A2  = 0.15625f * K4 * K4;          // +5u^2/32
    constexpr float A3  = -0.1171875f * K4 * K4 * K4;  // -15u^3/128
    float a    = s * tpn;                 // r*tp
    float be   = fmaf(-s, tnn, tn);       // (1-r)*tn
    float r    = s * INV;
    float stn  = s * tn;
    float aa   = a * a,   oma = 1.0f - a;
    float bb   = be * be, omb = 1.0f - be;
    float hp   = fmaf(aa, oma, oma);      // 1/(1+a)
    float he   = fmaf(bb, omb, omb);      // 1/(1+be)
    float omr2 = fmaf(-r, r, 1.0f);
    float psA  = omr2 * tp350;
    float A    = fmaf(psA, hp, s);        // s + ps
    float es   = ((2.0f - r) * stn) * he;
    float s1   = A - es;
    float s1s  = s1 * s1;
    float v    = s1s * s1s;               // s1^4
    float w1   = fmaf(v, A1, 1.0f);
    float w2   = fmaf(v, A3, A2);
    float v2   = v * v;
    float Q    = fmaf(v2, w2, w1);
    float s2   = s1 * Q;
    if (OUT) { ps_o = psA * hp; pc_o = s1 - s2; }   // off-chain
    return s2;
}

// ---------------- 256-step scan from global (prefetched), optional stats ----------------
template <int STATS>
__device__ __forceinline__ float scan256(float s, const float* __restrict__ p, int C,
                                         float& q0, float& q1, float& q2, float& q3) {
    if (STATS) g_ck[0][C] = s;
    float A[8], B[8];
#pragma unroll
    for (int k = 0; k < 8; k++) A[k] = __ldg(&p[k << 5]);
#pragma unroll
    for (int k = 0; k < 8; k++) B[k] = __ldg(&p[(8 + k) << 5]);
#pragma unroll 1
    for (int i0 = 0; i0 < 256; i0 += 16) {
#pragma unroll
        for (int k = 0; k < 8; k++) {
            float t3, tpn, tn, tnn, ps, pc;
            make_ops(A[k], t3, tpn, tn, tnn);
            s = gr_step<STATS>(s, t3, tpn, tn, tnn, ps, pc);
            if (STATS) { q0 += ps; q1 = fmaf(ps, ps, q1); q2 += pc; q3 = fmaf(pc, pc, q3); }
        }
#pragma unroll
        for (int k = 0; k < 8; k++) A[k] = __ldg(&p[(i0 + 16 + k) << 5]);  // pad absorbs overrun
#pragma unroll
        for (int k = 0; k < 8; k++) {
            float t3, tpn, tn, tnn, ps, pc;
            make_ops(B[k], t3, tpn, tn, tnn);
            s = gr_step<STATS>(s, t3, tpn, tn, tnn, ps, pc);
            if (STATS) { q0 += ps; q1 = fmaf(ps, ps, q1); q2 += pc; q3 = fmaf(pc, pc, q3); }
        }
#pragma unroll
        for (int k = 0; k < 8; k++) B[k] = __ldg(&p[(i0 + 24 + k) << 5]);
        if (STATS) {
            int nx = i0 + 16;
            if ((nx & 63) == 0 && nx < 256) g_ck[nx >> 6][C] = s;   // 64-step checkpoints
        }
    }
    return s;
}

// ---------------- kernel 1: fused load/transpose/pn-en stats + sweep 1 ----------------
__global__ void __launch_bounds__(32) k_s1(const float2* __restrict__ x) {
    __shared__ float ds[256][33];        // [step][chain] padded: conflict-free both ways
    int lane = threadIdx.x;
    int g    = blockIdx.x;
    const float2* xb = x + ((size_t)g << 13);   // 8192 timesteps per group
    float a0 = 0.f, a1 = 0.f, a2 = 0.f, a3 = 0.f;
#pragma unroll 4
    for (int k = 0; k < 256; k++) {
        int e = (k << 5) + lane;               // e = chain*256 + step (row-major in x)
        float2 v = __ldg(&xb[e]);              // coalesced
        float d  = v.x - v.y;
        float pn = fmaxf(d, 0.0f);
        float en = fmaxf(-d, 0.0f);
        a0 += pn; a1 = fmaf(pn, pn, a1);
        a2 += en; a3 = fmaf(en, en, a3);
        ds[e & 255][e >> 8] = d;               // stride-33 rows: conflict-free scatter
    }
    __syncwarp();
    // write transposed forcing for later kernels (coalesced)
    float* gd = g_d + (g << 13);
#pragma unroll 4
    for (int k = 0; k < 256; k++) {
        int e = (k << 5) + lane;               // e = (step<<5) | chain
        gd[e] = ds[e >> 5][e & 31];
    }
    // pn/en moment reduce (deterministic shfl tree)
#pragma unroll
    for (int o = 16; o > 0; o >>= 1) {
        a0 += __shfl_xor_sync(0xffffffffu, a0, o);
        a1 += __shfl_xor_sync(0xffffffffu, a1, o);
        a2 += __shfl_xor_sync(0xffffffffu, a2, o);
        a3 += __shfl_xor_sync(0xffffffffu, a3, o);
    }
    if (lane == 0) {
        g_prepart[g * 4 + 0] = a0; g_prepart[g * 4 + 1] = a1;
        g_prepart[g * 4 + 2] = a2; g_prepart[g * 4 + 3] = a3;
    }
    // sweep 1 from smem (init at equilibrium; chain 0 exact)
    int C = (g << 5) + lane;
    float s = (C == 0) ? 0.0f : S_EQ;
#pragma unroll 1
    for (int i0 = 0; i0 < 256; i0 += 8) {
        float dr[8];
#pragma unroll
        for (int k = 0; k < 8; k++) dr[k] = ds[i0 + k][lane];
#pragma unroll
        for (int k = 0; k < 8; k++) {
            float t3, tpn, tn, tnn, ps, pc;
            make_ops(dr[k], t3, tpn, tn, tnn);
            s = gr_step<0>(s, t3, tpn, tn, tnn, ps, pc);
        }
    }
    g_send0[C] = s;
}

// ---------------- kernel 2: sweep 2 + stats sweep, fused via per-group handoff ------
__global__ void __launch_bounds__(32) k_s23() {
    int lane = threadIdx.x;
    int g    = blockIdx.x;
    int C    = (g << 5) + lane;
    const float* p = g_d + (g << 13) + lane;
    float qq;                                  // dummy for non-stats scan
    // ---- sweep 2 (init from sweep-1 ends, history 256 -> 512)
    float s = (C == 0) ? 0.0f : g_send0[C - 1];
    s = scan256<0>(s, p, C, qq, qq, qq, qq);
    float s2end = s;
    if (lane == 31 && g < NG - 1) {            // publish handoff (last group has no consumer)
        *(volatile float*)&g_hand[g] = s2end;
        __threadfence();
        g_f2[g] = 1;
    }
    // ---- stats sweep init: predecessor's sweep-2 end
    float sin = __shfl_up_sync(0xffffffffu, s2end, 1);
    if (lane == 0) {
        if (g == 0) sin = 0.0f;
        else {
            while (g_f2[g - 1] == 0) __nanosleep(64);
            __threadfence();
            sin = *(volatile float*)&g_hand[g - 1];
            g_f2[g - 1] = 0;                   // single consumer resets (replay-safe)
        }
    }
    __syncwarp();
    // ---- stats sweep (history 512 at entry) + checkpoints
    float q0 = 0.f, q1 = 0.f, q2 = 0.f, q3 = 0.f;
    s = scan256<1>(sin, p, C, q0, q1, q2, q3);
#pragma unroll
    for (int o = 16; o > 0; o >>= 1) {
        q0 += __shfl_xor_sync(0xffffffffu, q0, o);
        q1 += __shfl_xor_sync(0xffffffffu, q1, o);
        q2 += __shfl_xor_sync(0xffffffffu, q2, o);
        q3 += __shfl_xor_sync(0xffffffffu, q3, o);
    }
    if (lane == 0) {
        g_spart[g * 4 + 0] = q0; g_spart[g * 4 + 1] = q1;
        g_spart[g * 4 + 2] = q2; g_spart[g * 4 + 3] = q3;
    }
}

// ---------------- kernel 3: combine partials -> mu / inv_sigma ----------------
__global__ void __launch_bounds__(256) k_statsk() {
    __shared__ float sd[8][256];
    int tx = threadIdx.x;                      // tx indexes the 256 groups directly
    float acc[8];
    acc[0] = g_prepart[tx * 4 + 0]; acc[1] = g_prepart[tx * 4 + 1];
    acc[2] = g_prepart[tx * 4 + 2]; acc[3] = g_prepart[tx * 4 + 3];
    acc[4] = g_spart[tx * 4 + 0];   acc[5] = g_spart[tx * 4 + 1];
    acc[6] = g_spart[tx * 4 + 2];   acc[7] = g_spart[tx * 4 + 3];
#pragma unroll
    for (int k = 0; k < 8; k++) sd[k][tx] = acc[k];
    __syncthreads();
    for (int o = 128; o > 0; o >>= 1) {
        if (tx < o) {
#pragma unroll
            for (int k = 0; k < 8; k++) sd[k][tx] += sd[k][tx + o];
        }
        __syncthreads();
    }
    if (tx == 0) {
        const float invT = 1.0f / (float)T_LEN;
        float S[4]  = {sd[0][0], sd[2][0], sd[4][0], sd[6][0]};
        float S2[4] = {sd[1][0], sd[3][0], sd[5][0], sd[7][0]};
#pragma unroll
        for (int k = 0; k < 4; k++) {
            float mu  = S[k] * invT;
            float var = fmaxf(S2[k] * invT - mu * mu, 0.0f);
            g_stats[k]     = mu;
            g_stats[4 + k] = 1.0f / sqrtf(var);
        }
    }
}

// ---------------- kernel 4: output, 64 steps/thread from checkpoints ----------------
__device__ __forceinline__ void o_phase(float& s, float* DB, const float* pp, int pre,
                                        float4 (*tout)[33], float (*tss)[33],
                                        int lane, int off, const float* st) {
#pragma unroll
    for (int k = 0; k < 8; k++) {
        float d  = DB[k];
        float pn = fmaxf(d, 0.0f);
        float en = fmaxf(-d, 0.0f);
        float t3, tpn, tn, tnn, ps, pc;
        make_ops(d, t3, tpn, tn, tnn);
        s = gr_step<1>(s, t3, tpn, tn, tnn, ps, pc);
        tout[lane][off + k] = make_float4((pn - st[0]) * st[4],
                                          (en - st[1]) * st[5],
                                          (ps - st[2]) * st[6],
                                          (pc - st[3]) * st[7]);
        tss[lane][off + k] = s;
    }
#pragma unroll
    for (int k = 0; k < 8; k++) DB[k] = __ldg(&pp[(pre + k) << 5]);
}

__global__ void __launch_bounds__(32) k_out(float4* __restrict__ out, float* __restrict__ ss) {
    __shared__ float4 tout[32][33];
    __shared__ float  tss[32][33];
    int lane = threadIdx.x;
    int cg = blockIdx.x >> 2;        // chain group (32 chains)
    int w  = blockIdx.x & 3;         // 64-step window
    int C  = (cg << 5) + lane;
    const float* pp = g_d + (cg << 13) + ((w << 6) << 5) + lane;
    float s = g_ck[w][C];
    float st[8];
#pragma unroll
    for (int k = 0; k < 8; k++) st[k] = g_stats[k];
    float DA[8], DB[8];
#pragma unroll
    for (int k = 0; k < 8; k++) DA[k] = __ldg(&pp[k << 5]);
#pragma unroll
    for (int k = 0; k < 8; k++) DB[k] = __ldg(&pp[(8 + k) << 5]);
    int rowbase = (cg << 13) + (w << 6);
#pragma unroll 1
    for (int t0 = 0; t0 < 64; t0 += 32) {
        o_phase(s, DA, pp, t0 + 16, tout, tss, lane, 0,  st);
        o_phase(s, DB, pp, t0 + 24, tout, tss, lane, 8,  st);
        o_phase(s, DA, pp, t0 + 32, tout, tss, lane, 16, st);  // pad absorbs overrun
        o_phase(s, DB, pp, t0 + 40, tout, tss, lane, 24, st);
        __syncwarp();
#pragma unroll 1
        for (int j = 0; j < 32; j++) {
            out[rowbase + j * 256 + t0 + lane] = tout[j][lane];   // 512B coalesced
            ss [rowbase + j * 256 + t0 + lane] = tss[j][lane];    // 128B coalesced
        }
        __syncwarp();
    }
}

// ---------------- launch ----------------
extern "C" void kernel_launch(void* const* d_in, const int* in_sizes, int n_in,
                              void* d_out, int out_size) {
    (void)in_sizes; (void)n_in; (void)out_size;
    const float2* x = (const float2*)d_in[0];
    float* out = (float*)d_out;                  // (T,4) normalized
    float* ssp = out + 4 * (size_t)T_LEN;        // (T,1) state trace

    k_s1<<<NG, 32>>>(x);                         // load+transpose+stats + sweep 1
    k_s23<<<NG, 32>>>();                         // sweep 2 + stats sweep (fused handoff)
    k_statsk<<<1, 256>>>();
    k_out<<<4 * NG, 32>>>((float4*)out, ssp);
}

// round 9
// speedup vs baseline: 1.1540x; 1.1540x over previous
#include <cuda_runtime.h>
#include <cuda_bf16.h>

// ---------------- constants ----------------
#define T_LEN (1 << 21)          // 2,097,152
#define B_CH  8192               // chains (256 steps each)
#define NPRE  2048               // k_pre blocks
#define NREF  64                 // refine blocks
#define S_EQ  166.0f             // stationary-state init for relaxation

// ---------------- device scratch ----------------
__device__ float g_d[T_LEN + 2048];     // transposed d = P - E; padded for prefetch overrun
__device__ float g_send[2][B_CH];       // ping-pong block end states
__device__ float g_ck[8][B_CH];         // 32-step checkpoints from stats pass
__device__ float g_prepart[NPRE * 4];   // Σpn, Σpn², Σen, Σen²
__device__ float g_spart[NREF * 4];     // Σps, Σps², Σpc, Σpc²
__device__ float g_stats[8];            // mu[4], inv_sigma[4]

// transposed index: idx(C,i) = ((C>>5)<<13) | (i<<5) | (C&31)

// ---------------- forcing -> step operands (bit-identical everywhere) ----------------
__device__ __forceinline__ void make_ops(float d, float& tp350, float& tpn,
                                         float& tn, float& tnn) {
    const float INV = 1.0f / 350.0f;
    float pn  = fmaxf(d, 0.0f);
    float en  = fmaxf(-d, 0.0f);
    float mp  = pn * INV;
    float mp2 = mp * mp;
    float gp  = fmaf(mp2, fmaf(mp2, 0.13333333f, -0.33333333f), 1.0f); // tanh(z)/z
    float me  = en * INV;
    float me2 = me * me;
    float ge  = fmaf(me2, fmaf(me2, 0.13333333f, -0.33333333f), 1.0f);
    tp350 = pn * gp;
    tpn   = (mp * gp) * INV;
    tn    = me * ge;
    tnn   = tn * INV;
}

// ---------------- MUFU-free GR4J step, 40-cycle chain (verified round 8) ----------------
// Invariants: tp,tn <= tanh(10/350)=0.02857, 0 <= s < 350.
template <int OUT>
__device__ __forceinline__ float gr_step(float s, float tp350, float tpn,
                                         float tn, float tnn,
                                         float& ps_o, float& pc_o) {
    const float INV = 1.0f / 350.0f;
    constexpr float C49 = 4.0f / (9.0f * 350.0f);
    constexpr float K4  = C49 * C49 * C49 * C49;
    constexpr float A1  = -0.25f * K4;                 // -u/4        (u = K4*v)
    constexpr float A2  = 0.15625f * K4 * K4;          // +5u^2/32
    constexpr float A3  = -0.1171875f * K4 * K4 * K4;  // -15u^3/128
    float a    = s * tpn;                 // r*tp
    float be   = fmaf(-s, tnn, tn);       // (1-r)*tn
    float r    = s * INV;
    float stn  = s * tn;
    float aa   = a * a,   oma = 1.0f - a;
    float bb   = be * be, omb = 1.0f - be;
    float hp   = fmaf(aa, oma, oma);      // 1/(1+a)
    float he   = fmaf(bb, omb, omb);      // 1/(1+be)
    float omr2 = fmaf(-r, r, 1.0f);
    float psA  = omr2 * tp350;
    float A    = fmaf(psA, hp, s);        // s + ps
    float es   = ((2.0f - r) * stn) * he;
    float s1   = A - es;
    float s1s  = s1 * s1;
    float v    = s1s * s1s;               // s1^4
    float w1   = fmaf(v, A1, 1.0f);
    float w2   = fmaf(v, A3, A2);
    float v2   = v * v;
    float Q    = fmaf(v2, w2, w1);
    float s2   = s1 * Q;
    if (OUT) { ps_o = psA * hp; pc_o = s1 - s2; }   // off-chain
    return s2;
}

// ---------------- prologue: d = P-E, transpose, pn/en stats ----------------
__global__ void __launch_bounds__(256) k_pre(const float2* __restrict__ x) {
    __shared__ float tile[32][33];
    __shared__ float red[4][256];
    int bid = blockIdx.x;
    int c0  = (bid >> 3) << 5;       // 32-chain group base
    int i0  = (bid & 7) << 5;        // 32-step tile base
    int tid = threadIdx.x;
    float a0 = 0.f, a1 = 0.f, a2 = 0.f, a3 = 0.f;
#pragma unroll
    for (int k = 0; k < 4; k++) {
        int e  = tid + (k << 8);
        int cc = e >> 5, ii = e & 31;
        float2 v = x[(c0 + cc) * 256 + i0 + ii];          // coalesced
        float d  = v.x - v.y;
        float pn = fmaxf(d, 0.0f);
        float en = fmaxf(-d, 0.0f);
        tile[cc][ii] = d;
        a0 += pn; a1 = fmaf(pn, pn, a1);
        a2 += en; a3 = fmaf(en, en, a3);
    }
    __syncthreads();
#pragma unroll
    for (int k = 0; k < 4; k++) {
        int e  = tid + (k << 8);
        int ii = e >> 5, cc = e & 31;
        g_d[((c0 >> 5) << 13) + ((i0 + ii) << 5) + cc] = tile[cc][ii];  // coalesced
    }
    red[0][tid] = a0; red[1][tid] = a1; red[2][tid] = a2; red[3][tid] = a3;
    __syncthreads();
    for (int o = 128; o > 0; o >>= 1) {
        if (tid < o) {
            red[0][tid] += red[0][tid + o]; red[1][tid] += red[1][tid + o];
            red[2][tid] += red[2][tid + o]; red[3][tid] += red[3][tid + o];
        }
        __syncthreads();
    }
    if (tid < 4) g_prepart[bid * 4 + tid] = red[tid][0];
}

// ---------------- refine pass (STATS also emits 32-step checkpoints + partials) --------
template <int FIRST, int STATS>
__global__ void __launch_bounds__(128) k_refine(int srcIdx, int dstIdx) {
    int C = blockIdx.x * 128 + threadIdx.x;
    const float* p = g_d + (((C >> 5) << 13) | (C & 31));
    float s = (C == 0) ? 0.0f : (FIRST ? S_EQ : g_send[srcIdx][C - 1]);
    float q0 = 0.f, q1 = 0.f, q2 = 0.f, q3 = 0.f;
    if (STATS) g_ck[0][C] = s;
    float A[8], B[8];
#pragma unroll
    for (int k = 0; k < 8; k++) A[k] = __ldg(&p[k << 5]);
#pragma unroll
    for (int k = 0; k < 8; k++) B[k] = __ldg(&p[(8 + k) << 5]);
#pragma unroll 1
    for (int i0 = 0; i0 < 256; i0 += 16) {
#pragma unroll
        for (int k = 0; k < 8; k++) {
            float t3, tpn, tn, tnn, ps, pc;
            make_ops(A[k], t3, tpn, tn, tnn);
            s = gr_step<STATS>(s, t3, tpn, tn, tnn, ps, pc);
            if (STATS) { q0 += ps; q1 = fmaf(ps, ps, q1); q2 += pc; q3 = fmaf(pc, pc, q3); }
        }
#pragma unroll
        for (int k = 0; k < 8; k++) A[k] = __ldg(&p[(i0 + 16 + k) << 5]);  // pad absorbs overrun
#pragma unroll
        for (int k = 0; k < 8; k++) {
            float t3, tpn, tn, tnn, ps, pc;
            make_ops(B[k], t3, tpn, tn, tnn);
            s = gr_step<STATS>(s, t3, tpn, tn, tnn, ps, pc);
            if (STATS) { q0 += ps; q1 = fmaf(ps, ps, q1); q2 += pc; q3 = fmaf(pc, pc, q3); }
        }
#pragma unroll
        for (int k = 0; k < 8; k++) B[k] = __ldg(&p[(i0 + 24 + k) << 5]);
        if (STATS) {
            int nx = i0 + 16;
            if ((nx & 31) == 0 && nx < 256) g_ck[nx >> 5][C] = s;  // 32-step checkpoint
        }
    }
    if (!STATS) g_send[dstIdx][C] = s;
    if (STATS) {
        __shared__ float rd[4][128];
        int tx = threadIdx.x;
        rd[0][tx] = q0; rd[1][tx] = q1; rd[2][tx] = q2; rd[3][tx] = q3;
        __syncthreads();
        for (int o = 64; o > 0; o >>= 1) {
            if (tx < o) {
                rd[0][tx] += rd[0][tx + o]; rd[1][tx] += rd[1][tx + o];
                rd[2][tx] += rd[2][tx + o]; rd[3][tx] += rd[3][tx + o];
            }
            __syncthreads();
        }
        if (tx < 4) g_spart[blockIdx.x * 4 + tx] = rd[tx][0];
    }
}

// ---------------- combine partials -> mu / inv_sigma ----------------
__global__ void __launch_bounds__(256) k_statsk() {
    __shared__ float sd[8][256];
    int tx = threadIdx.x;
    float acc[8] = {0, 0, 0, 0, 0, 0, 0, 0};
    for (int b = tx; b < NPRE; b += 256) {
        acc[0] += g_prepart[b * 4 + 0]; acc[1] += g_prepart[b * 4 + 1];
        acc[2] += g_prepart[b * 4 + 2]; acc[3] += g_prepart[b * 4 + 3];
    }
    if (tx < NREF) {
        acc[4] = g_spart[tx * 4 + 0]; acc[5] = g_spart[tx * 4 + 1];
        acc[6] = g_spart[tx * 4 + 2]; acc[7] = g_spart[tx * 4 + 3];
    }
#pragma unroll
    for (int k = 0; k < 8; k++) sd[k][tx] = acc[k];
    __syncthreads();
    for (int o = 128; o > 0; o >>= 1) {
        if (tx < o) {
#pragma unroll
            for (int k = 0; k < 8; k++) sd[k][tx] += sd[k][tx + o];
        }
        __syncthreads();
    }
    if (tx == 0) {
        const float invT = 1.0f / (float)T_LEN;
        float S[4]  = {sd[0][0], sd[2][0], sd[4][0], sd[6][0]};
        float S2[4] = {sd[1][0], sd[3][0], sd[5][0], sd[7][0]};
#pragma unroll
        for (int k = 0; k < 4; k++) {
            float mu  = S[k] * invT;
            float var = fmaxf(S2[k] * invT - mu * mu, 0.0f);
            g_stats[k]     = mu;
            g_stats[4 + k] = 1.0f / sqrtf(var);
        }
    }
}

// ---------------- output pass: 32 steps/thread from checkpoints (8x parallel) ------
__device__ __forceinline__ void o_phase(float& s, float* DB, const float* pp, int pre,
                                        float4 (*tout)[33], float (*tss)[33],
                                        int lane, int off, const float* st) {
#pragma unroll
    for (int k = 0; k < 8; k++) {
        float d  = DB[k];
        float pn = fmaxf(d, 0.0f);
        float en = fmaxf(-d, 0.0f);
        float t3, tpn, tn, tnn, ps, pc;
        make_ops(d, t3, tpn, tn, tnn);
        s = gr_step<1>(s, t3, tpn, tn, tnn, ps, pc);
        tout[lane][off + k] = make_float4((pn - st[0]) * st[4],
                                          (en - st[1]) * st[5],
                                          (ps - st[2]) * st[6],
                                          (pc - st[3]) * st[7]);
        tss[lane][off + k] = s;
    }
#pragma unroll
    for (int k = 0; k < 8; k++) DB[k] = __ldg(&pp[(pre + k) << 5]);
}

__global__ void __launch_bounds__(32) k_out(float4* __restrict__ out, float* __restrict__ ss) {
    __shared__ float4 tout[32][33];
    __shared__ float  tss[32][33];
    int lane = threadIdx.x;
    int cg = blockIdx.x >> 3;        // chain group (32 chains)
    int w  = blockIdx.x & 7;         // 32-step window
    int C  = (cg << 5) + lane;
    const float* pp = g_d + (cg << 13) + ((w << 5) << 5) + lane;
    float s = g_ck[w][C];
    float st[8];
#pragma unroll
    for (int k = 0; k < 8; k++) st[k] = g_stats[k];
    float DA[8], DB[8];
#pragma unroll
    for (int k = 0; k < 8; k++) DA[k] = __ldg(&pp[k << 5]);
#pragma unroll
    for (int k = 0; k < 8; k++) DB[k] = __ldg(&pp[(8 + k) << 5]);
    int rowbase = (cg << 13) + (w << 5);
    // single 32-step window (prefetch overrun lands in next window / pad)
    o_phase(s, DA, pp, 16, tout, tss, lane, 0,  st);
    o_phase(s, DB, pp, 24, tout, tss, lane, 8,  st);
    o_phase(s, DA, pp, 32, tout, tss, lane, 16, st);
    o_phase(s, DB, pp, 40, tout, tss, lane, 24, st);
    __syncwarp();
#pragma unroll 1
    for (int j = 0; j < 32; j++) {
        out[rowbase + j * 256 + lane] = tout[j][lane];   // 512B coalesced
        ss [rowbase + j * 256 + lane] = tss[j][lane];    // 128B coalesced
    }
}

// ---------------- launch ----------------
extern "C" void kernel_launch(void* const* d_in, const int* in_sizes, int n_in,
                              void* d_out, int out_size) {
    (void)in_sizes; (void)n_in; (void)out_size;
    const float2* x = (const float2*)d_in[0];
    float* out = (float*)d_out;                  // (T,4) normalized
    float* ssp = out + 4 * (size_t)T_LEN;        // (T,1) state trace

    k_pre<<<NPRE, 256>>>(x);
    k_refine<1, 0><<<NREF, 128>>>(0, 0);   // init at s*=166, history 256
    k_refine<0, 0><<<NREF, 128>>>(0, 1);   // history 512
    k_refine<0, 1><<<NREF, 128>>>(1, 0);   // stats + 32-step checkpoints (history 512)
    k_statsk<<<1, 256>>>();
    k_out<<<8 * (B_CH / 32), 32>>>((float4*)out, ssp);
}

// round 10
// speedup vs baseline: 1.1950x; 1.0355x over previous
#include <cuda_runtime.h>
#include <cuda_bf16.h>

// ---------------- constants ----------------
#define T_LEN (1 << 21)          // 2,097,152
#define B_CH  8192               // chains (256 steps each)
#define NPRE  2048               // k_pre blocks
#define NREF  64                 // refine blocks
#define S_EQ  166.0f             // stationary-state init for relaxation

// ---------------- device scratch ----------------
__device__ float g_d[T_LEN + 2048];     // transposed d = P - E; padded for prefetch overrun
__device__ float g_send[2][B_CH];       // ping-pong block end states
__device__ float g_ck[8][B_CH];         // 32-step checkpoints from stats pass
__device__ float g_prepart[NPRE * 4];   // Σpn, Σpn², Σen, Σen²
__device__ float g_spart[NREF * 4];     // Σps, Σps², Σpc, Σpc²
__device__ float g_stats[8];            // mu[4], inv_sigma[4]

// transposed index: idx(C,i) = ((C>>5)<<13) | (i<<5) | (C&31)

// ---------------- fused MUFU-free GR4J step on raw d ----------------
// pn/en mutually exclusive -> ONE tanh + ONE Pade denominator, FSEL-branched.
// Invariants: t <= tanh(10/350)=0.02857, 0 <= s < 350.
template <int OUT>
__device__ __forceinline__ float gr_d(float s, float d, float& ps_o, float& pc_o) {
    const float INV = 1.0f / 350.0f;
    constexpr float C49 = 4.0f / (9.0f * 350.0f);
    constexpr float K4  = C49 * C49 * C49 * C49;
    constexpr float A1  = -0.25f * K4;                 // -u/4        (u = K4*v)
    constexpr float A2  = 0.15625f * K4 * K4;          // +5u^2/32
    constexpr float A3  = -0.1171875f * K4 * K4 * K4;  // -15u^3/128
    bool  pos = d > 0.0f;
    float ad  = fabsf(d);
    // tanh(z)/z series, z = ad/350 <= 0.0286
    float m   = ad * INV;
    float m2  = m * m;
    float gi  = fmaf(m2, 0.13333333f, -0.33333333f);
    float go  = fmaf(m2, gi, 1.0f);
    float t   = m * go;          // tanh(z)
    float tIN = t * INV;         // tanh(z)/350
    float t350= ad * go;         // 350*tanh(z)
    // shared denominator: c = pos ? r*tp : (1-r)*tn  (identity: (1-r)*tn = t - s*t/350)
    float w   = s * tIN;
    float tmw = t - w;
    float c   = pos ? w : tmw;
    float cc  = c * c;
    float omc = 1.0f - c;
    float h   = fmaf(cc, omc, omc);       // 1/(1+c) + O(c^3)
    float hp  = pos ? h : 1.0f;
    float he  = pos ? 1.0f : h;
    float tp350 = pos ? t350 : 0.0f;
    float tn  = pos ? 0.0f : t;
    float r   = s * INV;
    float omr2= fmaf(-r, r, 1.0f);
    float psA = omr2 * tp350;
    float A   = fmaf(psA, hp, s);         // s + ps
    float stn = s * tn;
    float tmr = 2.0f - r;
    float e1  = tmr * stn;
    float es  = e1 * he;
    float s1  = A - es;
    float s1s = s1 * s1;
    float v   = s1s * s1s;                // s1^4
    float w1  = fmaf(v, A1, 1.0f);
    float w2  = fmaf(v, A3, A2);
    float v2  = v * v;
    float Q   = fmaf(v2, w2, w1);
    float s2  = s1 * Q;
    if (OUT) { ps_o = psA * hp; pc_o = s1 - s2; }   // off-chain
    return s2;
}

// ---------------- prologue: d = P-E, transpose, pn/en stats ----------------
__global__ void __launch_bounds__(256) k_pre(const float2* __restrict__ x) {
    __shared__ float tile[32][33];
    __shared__ float red[4][256];
    int bid = blockIdx.x;
    int c0  = (bid >> 3) << 5;       // 32-chain group base
    int i0  = (bid & 7) << 5;        // 32-step tile base
    int tid = threadIdx.x;
    float a0 = 0.f, a1 = 0.f, a2 = 0.f, a3 = 0.f;
#pragma unroll
    for (int k = 0; k < 4; k++) {
        int e  = tid + (k << 8);
        int cc = e >> 5, ii = e & 31;
        float2 v = x[(c0 + cc) * 256 + i0 + ii];          // coalesced
        float d  = v.x - v.y;
        float pn = fmaxf(d, 0.0f);
        float en = fmaxf(-d, 0.0f);
        tile[cc][ii] = d;
        a0 += pn; a1 = fmaf(pn, pn, a1);
        a2 += en; a3 = fmaf(en, en, a3);
    }
    __syncthreads();
#pragma unroll
    for (int k = 0; k < 4; k++) {
        int e  = tid + (k << 8);
        int ii = e >> 5, cc = e & 31;
        g_d[((c0 >> 5) << 13) + ((i0 + ii) << 5) + cc] = tile[cc][ii];  // coalesced
    }
    red[0][tid] = a0; red[1][tid] = a1; red[2][tid] = a2; red[3][tid] = a3;
    __syncthreads();
    for (int o = 128; o > 0; o >>= 1) {
        if (tid < o) {
            red[0][tid] += red[0][tid + o]; red[1][tid] += red[1][tid + o];
            red[2][tid] += red[2][tid + o]; red[3][tid] += red[3][tid + o];
        }
        __syncthreads();
    }
    if (tid < 4) g_prepart[bid * 4 + tid] = red[tid][0];
}

// ---------------- refine pass (STATS also emits 32-step checkpoints + partials) --------
template <int FIRST, int STATS>
__global__ void __launch_bounds__(128) k_refine(int srcIdx, int dstIdx) {
    int C = blockIdx.x * 128 + threadIdx.x;
    const float* p = g_d + (((C >> 5) << 13) | (C & 31));
    float s = (C == 0) ? 0.0f : (FIRST ? S_EQ : g_send[srcIdx][C - 1]);
    float q0 = 0.f, q1 = 0.f, q2 = 0.f, q3 = 0.f;
    if (STATS) g_ck[0][C] = s;
    float A[8], B[8];
#pragma unroll
    for (int k = 0; k < 8; k++) A[k] = __ldg(&p[k << 5]);
#pragma unroll
    for (int k = 0; k < 8; k++) B[k] = __ldg(&p[(8 + k) << 5]);
#pragma unroll 1
    for (int i0 = 0; i0 < 256; i0 += 16) {
#pragma unroll
        for (int k = 0; k < 8; k++) {
            float ps, pc;
            s = gr_d<STATS>(s, A[k], ps, pc);
            if (STATS) { q0 += ps; q1 = fmaf(ps, ps, q1); q2 += pc; q3 = fmaf(pc, pc, q3); }
        }
#pragma unroll
        for (int k = 0; k < 8; k++) A[k] = __ldg(&p[(i0 + 16 + k) << 5]);  // pad absorbs overrun
#pragma unroll
        for (int k = 0; k < 8; k++) {
            float ps, pc;
            s = gr_d<STATS>(s, B[k], ps, pc);
            if (STATS) { q0 += ps; q1 = fmaf(ps, ps, q1); q2 += pc; q3 = fmaf(pc, pc, q3); }
        }
#pragma unroll
        for (int k = 0; k < 8; k++) B[k] = __ldg(&p[(i0 + 24 + k) << 5]);
        if (STATS) {
            int nx = i0 + 16;
            if ((nx & 31) == 0 && nx < 256) g_ck[nx >> 5][C] = s;  // 32-step checkpoint
        }
    }
    if (!STATS) g_send[dstIdx][C] = s;
    if (STATS) {
        __shared__ float rd[4][128];
        int tx = threadIdx.x;
        rd[0][tx] = q0; rd[1][tx] = q1; rd[2][tx] = q2; rd[3][tx] = q3;
        __syncthreads();
        for (int o = 64; o > 0; o >>= 1) {
            if (tx < o) {
                rd[0][tx] += rd[0][tx + o]; rd[1][tx] += rd[1][tx + o];
                rd[2][tx] += rd[2][tx + o]; rd[3][tx] += rd[3][tx + o];
            }
            __syncthreads();
        }
        if (tx < 4) g_spart[blockIdx.x * 4 + tx] = rd[tx][0];
    }
}

// ---------------- combine partials -> mu / inv_sigma ----------------
__global__ void __launch_bounds__(256) k_statsk() {
    __shared__ float sd[8][256];
    int tx = threadIdx.x;
    float acc[8] = {0, 0, 0, 0, 0, 0, 0, 0};
    for (int b = tx; b < NPRE; b += 256) {
        acc[0] += g_prepart[b * 4 + 0]; acc[1] += g_prepart[b * 4 + 1];
        acc[2] += g_prepart[b * 4 + 2]; acc[3] += g_prepart[b * 4 + 3];
    }
    if (tx < NREF) {
        acc[4] = g_spart[tx * 4 + 0]; acc[5] = g_spart[tx * 4 + 1];
        acc[6] = g_spart[tx * 4 + 2]; acc[7] = g_spart[tx * 4 + 3];
    }
#pragma unroll
    for (int k = 0; k < 8; k++) sd[k][tx] = acc[k];
    __syncthreads();
    for (int o = 128; o > 0; o >>= 1) {
        if (tx < o) {
#pragma unroll
            for (int k = 0; k < 8; k++) sd[k][tx] += sd[k][tx + o];
        }
        __syncthreads();
    }
    if (tx == 0) {
        const float invT = 1.0f / (float)T_LEN;
        float S[4]  = {sd[0][0], sd[2][0], sd[4][0], sd[6][0]};
        float S2[4] = {sd[1][0], sd[3][0], sd[5][0], sd[7][0]};
#pragma unroll
        for (int k = 0; k < 4; k++) {
            float mu  = S[k] * invT;
            float var = fmaxf(S2[k] * invT - mu * mu, 0.0f);
            g_stats[k]     = mu;
            g_stats[4 + k] = 1.0f / sqrtf(var);
        }
    }
}

// ---------------- output pass: 32 steps/thread from checkpoints (8x parallel) ------
__device__ __forceinline__ void o_phase(float& s, float* DB, const float* pp, int pre,
                                        float4 (*tout)[33], float (*tss)[33],
                                        int lane, int off, const float* st) {
#pragma unroll
    for (int k = 0; k < 8; k++) {
        float d  = DB[k];
        float pn = fmaxf(d, 0.0f);
        float en = fmaxf(-d, 0.0f);
        float ps, pc;
        s = gr_d<1>(s, d, ps, pc);
        tout[lane][off + k] = make_float4((pn - st[0]) * st[4],
                                          (en - st[1]) * st[5],
                                          (ps - st[2]) * st[6],
                                          (pc - st[3]) * st[7]);
        tss[lane][off + k] = s;
    }
#pragma unroll
    for (int k = 0; k < 8; k++) DB[k] = __ldg(&pp[(pre + k) << 5]);
}

__global__ void __launch_bounds__(32) k_out(float4* __restrict__ out, float* __restrict__ ss) {
    __shared__ float4 tout[32][33];
    __shared__ float  tss[32][33];
    int lane = threadIdx.x;
    int cg = blockIdx.x >> 3;        // chain group (32 chains)
    int w  = blockIdx.x & 7;         // 32-step window
    int C  = (cg << 5) + lane;
    const float* pp = g_d + (cg << 13) + ((w << 5) << 5) + lane;
    float s = g_ck[w][C];
    float st[8];
#pragma unroll
    for (int k = 0; k < 8; k++) st[k] = g_stats[k];
    float DA[8], DB[8];
#pragma unroll
    for (int k = 0; k < 8; k++) DA[k] = __ldg(&pp[k << 5]);
#pragma unroll
    for (int k = 0; k < 8; k++) DB[k] = __ldg(&pp[(8 + k) << 5]);
    int rowbase = (cg << 13) + (w << 5);
    // single 32-step window (prefetch overrun lands in next window / pad)
    o_phase(s, DA, pp, 16, tout, tss, lane, 0,  st);
    o_phase(s, DB, pp, 24, tout, tss, lane, 8,  st);
    o_phase(s, DA, pp, 32, tout, tss, lane, 16, st);
    o_phase(s, DB, pp, 40, tout, tss, lane, 24, st);
    __syncwarp();
#pragma unroll 1
    for (int j = 0; j < 32; j++) {
        out[rowbase + j * 256 + lane] = tout[j][lane];   // 512B coalesced
        ss [rowbase + j * 256 + lane] = tss[j][lane];    // 128B coalesced
    }
}

// ---------------- launch ----------------
extern "C" void kernel_launch(void* const* d_in, const int* in_sizes, int n_in,
                              void* d_out, int out_size) {
    (void)in_sizes; (void)n_in; (void)out_size;
    const float2* x = (const float2*)d_in[0];
    float* out = (float*)d_out;                  // (T,4) normalized
    float* ssp = out + 4 * (size_t)T_LEN;        // (T,1) state trace

    k_pre<<<NPRE, 256>>>(x);
    k_refine<1, 0><<<NREF, 128>>>(0, 0);   // init at s*=166, history 256
    k_refine<0, 0><<<NREF, 128>>>(0, 1);   // history 512
    k_refine<0, 1><<<NREF, 128>>>(1, 0);   // stats + 32-step checkpoints (history 512)
    k_statsk<<<1, 256>>>();
    k_out<<<8 * (B_CH / 32), 32>>>((float4*)out, ssp);
}

// round 12
// speedup vs baseline: 1.3712x; 1.1474x over previous
#include <cuda_runtime.h>
#include <cuda_bf16.h>

// ---------------- constants ----------------
#define T_LEN (1 << 21)          // 2,097,152
#define B_CH  8192               // chains (256 steps each)
#define NPRE  2048               // k_pre blocks
#define NREF  64                 // refine blocks
#define S_EQS (166.0f / 350.0f)  // stationary init in sigma units

// ---------------- device scratch ----------------
// packed quads: 4 consecutive steps of one chain per float4.
// float4 index: ((C>>5)<<11) + ((i>>2)<<5) + (C&31)
__device__ float4 g_d4[(T_LEN / 4) + 1024];  // + pad for prefetch overrun
__device__ float  g_send[2][B_CH];           // ping-pong block end states (sigma)
__device__ float  g_ck[8][B_CH];             // 32-step checkpoints (sigma)
__device__ float  g_prepart[NPRE * 4];       // Σpn, Σpn², Σen, Σen²
__device__ float  g_spart[NREF * 4];         // Σps, Σps², Σpc, Σpc² (rescaled)
__device__ float  g_stats[8];                // mu[4], inv_sigma[4]

// ---------------- signed tanh (d-only; hoisted off the chain) ----------------
__device__ __forceinline__ float tanh_s(float d) {
    const float INV = 1.0f / 350.0f;
    float m = d * INV;                                  // |m| <= 0.0286
    return m * fmaf(m * m, -0.33333333f, 1.0f);        // odd series, rel err ~9e-8
}

// ---------------- sigma-space GR4J step (~20 FMA on-chain) ----------------
// sg = s/350 in [0,1); ts = tanh(d/350) signed.
template <int OUT>
__device__ __forceinline__ float grs(float sg, float ts, float& psig, float& pcsig) {
    constexpr float K9 = 4.0f / 9.0f;
    constexpr float KQ = K9 * K9 * K9 * K9;            // u = KQ * sg1^4
    constexpr float A1 = -0.25f * KQ;
    constexpr float A2 = 0.15625f * KQ * KQ;
    constexpr float A3 = -0.1171875f * KQ * KQ * KQ;
    float tp  = fmaxf(ts, 0.0f);                       // ALU
    float tn  = fmaxf(-ts, 0.0f);                      // ALU
    float w   = sg * fabsf(ts);                        // sigma*t
    float tmw = fabsf(ts) - w;                         // (1-sigma)*t
    float c   = (ts > 0.0f) ? w : tmw;                 // shared Pade arg
    float omc = 1.0f - c;
    float h   = fmaf(c * c, omc, omc);                 // 1/(1+c) + O(c^3)
    float omr2 = fmaf(-sg, sg, 1.0f);
    float psA  = omr2 * tp;                            // ps/350 before h
    float A    = fmaf(psA, h, sg);                     // sigma + ps/350
    float stn  = sg * tn;
    float e1   = (2.0f - sg) * stn;
    float es   = e1 * h;                               // es/350
    float s1   = A - es;
    float s1s  = s1 * s1;
    float v    = s1s * s1s;                            // s1^4
    float w1   = fmaf(v, A1, 1.0f);
    float w2   = fmaf(v, A3, A2);
    float Q    = fmaf(v * v, w2, w1);
    float s2   = s1 * Q;
    if (OUT) { psig = psA * h; pcsig = s1 - s2; }      // off-chain (sigma units)
    return s2;
}

// ---------------- prologue: d = P-E, packed transpose, pn/en stats ----------------
__global__ void __launch_bounds__(256) k_pre(const float2* __restrict__ x) {
    __shared__ float tile[32][33];
    __shared__ float red[4][256];
    int bid = blockIdx.x;
    int c0  = (bid >> 3) << 5;       // 32-chain group base
    int i0  = (bid & 7) << 5;        // 32-step tile base
    int tid = threadIdx.x;
    float a0 = 0.f, a1 = 0.f, a2 = 0.f, a3 = 0.f;
#pragma unroll
    for (int k = 0; k < 4; k++) {
        int e  = tid + (k << 8);
        int cc = e >> 5, ii = e & 31;
        float2 v = x[(c0 + cc) * 256 + i0 + ii];          // coalesced
        float d  = v.x - v.y;
        float pn = fmaxf(d, 0.0f);
        float en = fmaxf(-d, 0.0f);
        tile[cc][ii] = d;
        a0 += pn; a1 = fmaf(pn, pn, a1);
        a2 += en; a3 = fmaf(en, en, a3);
    }
    __syncthreads();
    {   // packed quad write: thread -> (chain cc, quad qq)
        int cc = tid & 31, qq = tid >> 5;                 // qq in 0..7
        float4 v4 = make_float4(tile[cc][qq * 4 + 0], tile[cc][qq * 4 + 1],
                                tile[cc][qq * 4 + 2], tile[cc][qq * 4 + 3]);
        g_d4[((c0 >> 5) << 11) + (((i0 >> 2) + qq) << 5) + cc] = v4;  // coalesced 512B
    }
    red[0][tid] = a0; red[1][tid] = a1; red[2][tid] = a2; red[3][tid] = a3;
    __syncthreads();
    for (int o = 128; o > 0; o >>= 1) {
        if (tid < o) {
            red[0][tid] += red[0][tid + o]; red[1][tid] += red[1][tid + o];
            red[2][tid] += red[2][tid + o]; red[3][tid] += red[3][tid + o];
        }
        __syncthreads();
    }
    if (tid < 4) g_prepart[bid * 4 + tid] = red[tid][0];
}

// ---------------- refine pass (STATS also emits checkpoints + partials) --------
template <int FIRST, int STATS>
__global__ void __launch_bounds__(128) k_refine(int srcIdx, int dstIdx) {
    int C = blockIdx.x * 128 + threadIdx.x;
    const float4* pq = g_d4 + ((C >> 5) << 11) + (C & 31);
    float sg = (C == 0) ? 0.0f : (FIRST ? S_EQS : g_send[srcIdx][C - 1]);
    float q0 = 0.f, q1 = 0.f, q2 = 0.f, q3 = 0.f;
    if (STATS) g_ck[0][C] = sg;
    float4 QA[4], QB[4];
#pragma unroll
    for (int k = 0; k < 4; k++) QA[k] = __ldg(&pq[k << 5]);          // steps 0-15
#pragma unroll
    for (int k = 0; k < 4; k++) QB[k] = __ldg(&pq[(4 + k) << 5]);    // steps 16-31
#pragma unroll 1
    for (int i0 = 0; i0 < 256; i0 += 32) {
        float ts[16];
#pragma unroll
        for (int k = 0; k < 4; k++) {
            ts[4 * k + 0] = tanh_s(QA[k].x); ts[4 * k + 1] = tanh_s(QA[k].y);
            ts[4 * k + 2] = tanh_s(QA[k].z); ts[4 * k + 3] = tanh_s(QA[k].w);
        }
#pragma unroll
        for (int k = 0; k < 4; k++) QA[k] = __ldg(&pq[((i0 >> 2) + 8 + k) << 5]);
#pragma unroll
        for (int j = 0; j < 16; j++) {
            float ps, pc;
            sg = grs<STATS>(sg, ts[j], ps, pc);
            if (STATS) { q0 += ps; q1 = fmaf(ps, ps, q1); q2 += pc; q3 = fmaf(pc, pc, q3); }
        }
#pragma unroll
        for (int k = 0; k < 4; k++) {
            ts[4 * k + 0] = tanh_s(QB[k].x); ts[4 * k + 1] = tanh_s(QB[k].y);
            ts[4 * k + 2] = tanh_s(QB[k].z); ts[4 * k + 3] = tanh_s(QB[k].w);
        }
#pragma unroll
        for (int k = 0; k < 4; k++) QB[k] = __ldg(&pq[((i0 >> 2) + 12 + k) << 5]);
#pragma unroll
        for (int j = 0; j < 16; j++) {
            float ps, pc;
            sg = grs<STATS>(sg, ts[j], ps, pc);
            if (STATS) { q0 += ps; q1 = fmaf(ps, ps, q1); q2 += pc; q3 = fmaf(pc, pc, q3); }
        }
        if (STATS) {
            int nx = i0 + 32;
            if (nx < 256) g_ck[nx >> 5][C] = sg;                     // 32-step checkpoint
        }
    }
    if (!STATS) g_send[dstIdx][C] = sg;
    if (STATS) {
        // rescale sigma-unit sums to physical units once
        q0 *= 350.0f; q1 *= 122500.0f; q2 *= 350.0f; q3 *= 122500.0f;
        __shared__ float rd[4][128];
        int tx = threadIdx.x;
        rd[0][tx] = q0; rd[1][tx] = q1; rd[2][tx] = q2; rd[3][tx] = q3;
        __syncthreads();
        for (int o = 64; o > 0; o >>= 1) {
            if (tx < o) {
                rd[0][tx] += rd[0][tx + o]; rd[1][tx] += rd[1][tx + o];
                rd[2][tx] += rd[2][tx + o]; rd[3][tx] += rd[3][tx + o];
            }
            __syncthreads();
        }
        if (tx < 4) g_spart[blockIdx.x * 4 + tx] = rd[tx][0];
    }
}

// ---------------- combine partials -> mu / inv_sigma ----------------
__global__ void __launch_bounds__(256) k_statsk() {
    __shared__ float sd[8][256];
    int tx = threadIdx.x;
    float acc[8] = {0, 0, 0, 0, 0, 0, 0, 0};
    for (int b = tx; b < NPRE; b += 256) {
        acc[0] += g_prepart[b * 4 + 0]; acc[1] += g_prepart[b * 4 + 1];
        acc[2] += g_prepart[b * 4 + 2]; acc[3] += g_prepart[b * 4 + 3];
    }
    if (tx < NREF) {
        acc[4] = g_spart[tx * 4 + 0]; acc[5] = g_spart[tx * 4 + 1];
        acc[6] = g_spart[tx * 4 + 2]; acc[7] = g_spart[tx * 4 + 3];
    }
#pragma unroll
    for (int k = 0; k < 8; k++) sd[k][tx] = acc[k];
    __syncthreads();
    for (int o = 128; o > 0; o >>= 1) {
        if (tx < o) {
#pragma unroll
            for (int k = 0; k < 8; k++) sd[k][tx] += sd[k][tx + o];
        }
        __syncthreads();
    }
    if (tx == 0) {
        const float invT = 1.0f / (float)T_LEN;
        float S[4]  = {sd[0][0], sd[2][0], sd[4][0], sd[6][0]};
        float S2[4] = {sd[1][0], sd[3][0], sd[5][0], sd[7][0]};
#pragma unroll
        for (int k = 0; k < 4; k++) {
            float mu  = S[k] * invT;
            float var = fmaxf(S2[k] * invT - mu * mu, 0.0f);
            g_stats[k]     = mu;
            g_stats[4 + k] = 1.0f / sqrtf(var);
        }
    }
}

// ---------------- output pass: 32 steps/thread from checkpoints ----------------
__global__ void __launch_bounds__(32) k_out(float4* __restrict__ out, float* __restrict__ ss) {
    __shared__ float4 tout[32][33];
    __shared__ float  tss[32][33];
    int lane = threadIdx.x;
    int cg = blockIdx.x >> 3;        // chain group (32 chains)
    int w  = blockIdx.x & 7;         // 32-step window
    int C  = (cg << 5) + lane;
    const float4* pq = g_d4 + (cg << 11) + lane;
    float sg = g_ck[w][C];
    // normalization constants (fold 350x rescale for ps/pc/ss)
    float c0 = g_stats[4],          o0 = g_stats[0] * g_stats[4];
    float c1 = g_stats[5],          o1 = g_stats[1] * g_stats[5];
    float c2 = 350.0f * g_stats[6], o2 = g_stats[2] * g_stats[6];
    float c3 = 350.0f * g_stats[7], o3 = g_stats[3] * g_stats[7];
    float4 Qd[8];
#pragma unroll
    for (int k = 0; k < 8; k++) Qd[k] = __ldg(&pq[((w << 3) + k) << 5]);
#pragma unroll
    for (int q = 0; q < 8; q++) {
        float dv[4] = {Qd[q].x, Qd[q].y, Qd[q].z, Qd[q].w};
#pragma unroll
        for (int j = 0; j < 4; j++) {
            float d  = dv[j];
            float pn = fmaxf(d, 0.0f);
            float en = fmaxf(-d, 0.0f);
            float ps, pc;
            sg = grs<1>(sg, tanh_s(d), ps, pc);
            tout[lane][q * 4 + j] = make_float4(fmaf(pn, c0, -o0),
                                                fmaf(en, c1, -o1),
                                                fmaf(ps, c2, -o2),
                                                fmaf(pc, c3, -o3));
            tss[lane][q * 4 + j] = 350.0f * sg;
        }
    }
    __syncwarp();
    int rowbase = (cg << 13) + (w << 5);
#pragma unroll 1
    for (int j = 0; j < 32; j++) {
        out[rowbase + j * 256 + lane] = tout[j][lane];   // 512B coalesced
        ss [rowbase + j * 256 + lane] = tss[j][lane];    // 128B coalesced
    }
}

// ---------------- launch ----------------
extern "C" void kernel_launch(void* const* d_in, const int* in_sizes, int n_in,
                              void* d_out, int out_size) {
    (void)in_sizes; (void)n_in; (void)out_size;
    const float2* x = (const float2*)d_in[0];
    float* out = (float*)d_out;                  // (T,4) normalized
    float* ssp = out + 4 * (size_t)T_LEN;        // (T,1) state trace

    k_pre<<<NPRE, 256>>>(x);
    k_refine<1, 0><<<NREF, 128>>>(0, 0);   // init at sigma*=0.474, history 256
    k_refine<0, 0><<<NREF, 128>>>(0, 1);   // history 512
    k_refine<0, 1><<<NREF, 128>>>(1, 0);   // stats + 32-step checkpoints (history 512)
    k_statsk<<<1, 256>>>();
    k_out<<<8 * (B_CH / 32), 32>>>((float4*)out, ssp);
}

// round 13
// speedup vs baseline: 1.4235x; 1.0381x over previous
#include <cuda_runtime.h>
#include <cuda_bf16.h>

// ---------------- constants ----------------
#define T_LEN (1 << 21)          // 2,097,152
#define B_CH  8192               // chains (256 steps each)
#define NPRE  2048               // k_pre blocks
#define NREF  64                 // refine blocks
#define S_EQS (166.0f / 350.0f)  // stationary init in sigma units

// ---------------- device scratch ----------------
// packed quads: 4 consecutive steps of one chain per float4.
// float4 index: ((C>>5)<<11) + ((i>>2)<<5) + (C&31)
__device__ float4 g_d4[(T_LEN / 4) + 1024];  // + pad for prefetch overrun
__device__ float  g_send[2][B_CH];           // ping-pong block end states (sigma)
__device__ float  g_ck[16][B_CH];            // 16-step checkpoints (sigma)
__device__ float  g_prepart[NPRE * 4];       // Σpn, Σpn², Σen, Σen²
__device__ float  g_spart[NREF * 4];         // Σps, Σps², Σpc, Σpc² (rescaled)
__device__ float  g_stats[8];                // mu[4], inv_sigma[4]
__device__ int    g_done;                    // stats-finalize ticket (reset each use)

// ---------------- signed tanh (d-only; hoisted off the chain) ----------------
__device__ __forceinline__ float tanh_s(float d) {
    const float INV = 1.0f / 350.0f;
    float m = d * INV;                                  // |m| <= 0.0286
    return m * fmaf(m * m, -0.33333333f, 1.0f);        // odd series, rel err ~9e-8
}

// ---------------- merged sigma-space GR4J step (~17 FMA) ----------------
// sg in [0,1); ts = tanh(d/350) signed. One update path:
//   s1 = sg + z*h,  z = |t| * (pos ? 1-sg^2 : sg^2-2sg),  h = 1/(1+c),
//   c  = pos ? sg*|t| : (1-sg)*|t|
template <int OUT>
__device__ __forceinline__ float grs(float sg, float ts, float& ps_o, float& pc_o) {
    constexpr float K9 = 4.0f / 9.0f;
    constexpr float KQ = K9 * K9 * K9 * K9;            // u = KQ * s1^4
    constexpr float A1 = -0.25f * KQ;
    constexpr float A2 = 0.15625f * KQ * KQ;
    constexpr float A3 = -0.1171875f * KQ * KQ * KQ;
    bool  pos = ts > 0.0f;
    float at  = fabsf(ts);
    float w   = sg * at;                               // sigma*t
    float tmw = at - w;                                // (1-sigma)*t
    float c   = pos ? w : tmw;                         // shared Pade arg
    float omc = 1.0f - c;
    float h   = fmaf(c * c, omc, omc);                 // 1/(1+c) + O(c^3)
    float g1  = sg * sg;
    float mp  = 1.0f - g1;                             // pos:  1 - sg^2
    float mn  = fmaf(-2.0f, sg, g1);                   // neg:  sg^2 - 2 sg
    float m1  = pos ? mp : mn;
    float z   = m1 * at;
    float s1  = fmaf(z, h, sg);                        // sg + ps  (or sg - es)
    float s1s = s1 * s1;
    float v   = s1s * s1s;                             // s1^4
    float w1  = fmaf(v, A1, 1.0f);
    float w2  = fmaf(v, A3, A2);
    float Q   = fmaf(v * v, w2, w1);
    float s2  = s1 * Q;
    if (OUT) {                                         // off-chain
        ps_o = fmaxf(s1 - sg, 0.0f);                   // ps (0 in neg case)
        pc_o = s1 - s2;                                // perc
    }
    return s2;
}

// ---------------- prologue: d = P-E, packed transpose, pn/en stats ----------------
__global__ void __launch_bounds__(256) k_pre(const float2* __restrict__ x) {
    __shared__ float tile[32][33];
    __shared__ float red[4][256];
    int bid = blockIdx.x;
    int c0  = (bid >> 3) << 5;       // 32-chain group base
    int i0  = (bid & 7) << 5;        // 32-step tile base
    int tid = threadIdx.x;
    float a0 = 0.f, a1 = 0.f, a2 = 0.f, a3 = 0.f;
#pragma unroll
    for (int k = 0; k < 4; k++) {
        int e  = tid + (k << 8);
        int cc = e >> 5, ii = e & 31;
        float2 v = x[(c0 + cc) * 256 + i0 + ii];          // coalesced
        float d  = v.x - v.y;
        float pn = fmaxf(d, 0.0f);
        float en = fmaxf(-d, 0.0f);
        tile[cc][ii] = d;
        a0 += pn; a1 = fmaf(pn, pn, a1);
        a2 += en; a3 = fmaf(en, en, a3);
    }
    __syncthreads();
    {   // packed quad write: thread -> (chain cc, quad qq)
        int cc = tid & 31, qq = tid >> 5;                 // qq in 0..7
        float4 v4 = make_float4(tile[cc][qq * 4 + 0], tile[cc][qq * 4 + 1],
                                tile[cc][qq * 4 + 2], tile[cc][qq * 4 + 3]);
        g_d4[((c0 >> 5) << 11) + (((i0 >> 2) + qq) << 5) + cc] = v4;  // coalesced 512B
    }
    red[0][tid] = a0; red[1][tid] = a1; red[2][tid] = a2; red[3][tid] = a3;
    __syncthreads();
    for (int o = 128; o > 0; o >>= 1) {
        if (tid < o) {
            red[0][tid] += red[0][tid + o]; red[1][tid] += red[1][tid + o];
            red[2][tid] += red[2][tid + o]; red[3][tid] += red[3][tid + o];
        }
        __syncthreads();
    }
    if (tid < 4) g_prepart[bid * 4 + tid] = red[tid][0];
}

// ---------------- refine pass (STATS: checkpoints + partials + fused finalize) -----
template <int FIRST, int STATS>
__global__ void __launch_bounds__(128) k_refine(int srcIdx, int dstIdx) {
    int C = blockIdx.x * 128 + threadIdx.x;
    const float4* pq = g_d4 + ((C >> 5) << 11) + (C & 31);
    float sg = (C == 0) ? 0.0f : (FIRST ? S_EQS : g_send[srcIdx][C - 1]);
    float q0 = 0.f, q1 = 0.f, q2 = 0.f, q3 = 0.f;
    if (STATS) g_ck[0][C] = sg;
    float4 QA[4], QB[4];
#pragma unroll
    for (int k = 0; k < 4; k++) QA[k] = __ldg(&pq[k << 5]);          // steps 0-15
#pragma unroll
    for (int k = 0; k < 4; k++) QB[k] = __ldg(&pq[(4 + k) << 5]);    // steps 16-31
#pragma unroll 1
    for (int i0 = 0; i0 < 256; i0 += 32) {
        float ts[16];
#pragma unroll
        for (int k = 0; k < 4; k++) {
            ts[4 * k + 0] = tanh_s(QA[k].x); ts[4 * k + 1] = tanh_s(QA[k].y);
            ts[4 * k + 2] = tanh_s(QA[k].z); ts[4 * k + 3] = tanh_s(QA[k].w);
        }
#pragma unroll
        for (int k = 0; k < 4; k++) QA[k] = __ldg(&pq[((i0 >> 2) + 8 + k) << 5]);
#pragma unroll
        for (int j = 0; j < 16; j++) {
            float ps, pc;
            sg = grs<STATS>(sg, ts[j], ps, pc);
            if (STATS) { q0 += ps; q1 = fmaf(ps, ps, q1); q2 += pc; q3 = fmaf(pc, pc, q3); }
        }
        if (STATS) g_ck[(i0 >> 4) + 1][C] = sg;                      // step i0+16
#pragma unroll
        for (int k = 0; k < 4; k++) {
            ts[4 * k + 0] = tanh_s(QB[k].x); ts[4 * k + 1] = tanh_s(QB[k].y);
            ts[4 * k + 2] = tanh_s(QB[k].z); ts[4 * k + 3] = tanh_s(QB[k].w);
        }
#pragma unroll
        for (int k = 0; k < 4; k++) QB[k] = __ldg(&pq[((i0 >> 2) + 12 + k) << 5]);
#pragma unroll
        for (int j = 0; j < 16; j++) {
            float ps, pc;
            sg = grs<STATS>(sg, ts[j], ps, pc);
            if (STATS) { q0 += ps; q1 = fmaf(ps, ps, q1); q2 += pc; q3 = fmaf(pc, pc, q3); }
        }
        if (STATS) {
            int nx = i0 + 32;
            if (nx < 256) g_ck[nx >> 4][C] = sg;                     // step i0+32
        }
    }
    if (!STATS) g_send[dstIdx][C] = sg;
    if (STATS) {
        // rescale sigma-unit sums to physical units once
        q0 *= 350.0f; q1 *= 122500.0f; q2 *= 350.0f; q3 *= 122500.0f;
        __shared__ float rd[4][128];
        __shared__ int lastf;
        int tx = threadIdx.x;
        rd[0][tx] = q0; rd[1][tx] = q1; rd[2][tx] = q2; rd[3][tx] = q3;
        __syncthreads();
        for (int o = 64; o > 0; o >>= 1) {
            if (tx < o) {
                rd[0][tx] += rd[0][tx + o]; rd[1][tx] += rd[1][tx + o];
                rd[2][tx] += rd[2][tx + o]; rd[3][tx] += rd[3][tx + o];
            }
            __syncthreads();
        }
        if (tx < 4) g_spart[blockIdx.x * 4 + tx] = rd[tx][0];
        __threadfence();
        if (tx == 0) lastf = (atomicAdd(&g_done, 1) == NREF - 1);
        __syncthreads();
        if (lastf) {   // last-arriving block finalizes mu / inv_sigma
            __threadfence();
            __shared__ float sd[8][128];
            float acc[8] = {0, 0, 0, 0, 0, 0, 0, 0};
            for (int b = tx; b < NPRE; b += 128) {
                acc[0] += g_prepart[b * 4 + 0]; acc[1] += g_prepart[b * 4 + 1];
                acc[2] += g_prepart[b * 4 + 2]; acc[3] += g_prepart[b * 4 + 3];
            }
            if (tx < NREF) {
                acc[4] = g_spart[tx * 4 + 0]; acc[5] = g_spart[tx * 4 + 1];
                acc[6] = g_spart[tx * 4 + 2]; acc[7] = g_spart[tx * 4 + 3];
            }
#pragma unroll
            for (int k = 0; k < 8; k++) sd[k][tx] = acc[k];
            __syncthreads();
            for (int o = 64; o > 0; o >>= 1) {
                if (tx < o) {
#pragma unroll
                    for (int k = 0; k < 8; k++) sd[k][tx] += sd[k][tx + o];
                }
                __syncthreads();
            }
            if (tx == 0) {
                const float invT = 1.0f / (float)T_LEN;
                float S[4]  = {sd[0][0], sd[2][0], sd[4][0], sd[6][0]};
                float S2[4] = {sd[1][0], sd[3][0], sd[5][0], sd[7][0]};
#pragma unroll
                for (int k = 0; k < 4; k++) {
                    float mu  = S[k] * invT;
                    float var = fmaxf(S2[k] * invT - mu * mu, 0.0f);
                    g_stats[k]     = mu;
                    g_stats[4 + k] = 1.0f / sqrtf(var);
                }
                g_done = 0;     // reset ticket for next graph replay
            }
        }
    }
}

// ---------------- output pass: 16 steps/warp from checkpoints ----------------
__global__ void __launch_bounds__(64) k_out(float4* __restrict__ out, float* __restrict__ ss) {
    __shared__ float4 tout[32][33];
    __shared__ float  tss[32][33];
    int tid  = threadIdx.x;
    int lane = tid & 31;
    int wp   = tid >> 5;             // warp 0/1
    int cg   = blockIdx.x >> 3;      // chain group (32 chains)
    int b    = blockIdx.x & 7;       // 32-step tile index
    int w    = (b << 1) + wp;        // 16-step window index (0..15)
    int C    = (cg << 5) + lane;
    const float4* pq = g_d4 + (cg << 11) + lane;
    float sg = g_ck[w][C];
    // normalization constants (fold 350x rescale for ps/pc/ss)
    float c0 = g_stats[4],          o0 = g_stats[0] * g_stats[4];
    float c1 = g_stats[5],          o1 = g_stats[1] * g_stats[5];
    float c2 = 350.0f * g_stats[6], o2 = g_stats[2] * g_stats[6];
    float c3 = 350.0f * g_stats[7], o3 = g_stats[3] * g_stats[7];
    float4 Qd[4];
#pragma unroll
    for (int k = 0; k < 4; k++) Qd[k] = __ldg(&pq[((w << 2) + k) << 5]);
    int colbase = wp << 4;           // this warp's 16 columns within the 32-step tile
#pragma unroll
    for (int q = 0; q < 4; q++) {
        float dv[4] = {Qd[q].x, Qd[q].y, Qd[q].z, Qd[q].w};
#pragma unroll
        for (int j = 0; j < 4; j++) {
            float d  = dv[j];
            float pn = fmaxf(d, 0.0f);
            float en = fmaxf(-d, 0.0f);
            float ps, pc;
            sg = grs<1>(sg, tanh_s(d), ps, pc);
            tout[lane][colbase + q * 4 + j] = make_float4(fmaf(pn, c0, -o0),
                                                          fmaf(en, c1, -o1),
                                                          fmaf(ps, c2, -o2),
                                                          fmaf(pc, c3, -o3));
            tss[lane][colbase + q * 4 + j] = 350.0f * sg;
        }
    }
    __syncthreads();
    int rowstart = (cg << 13) + (b << 5);
#pragma unroll 1
    for (int e = tid; e < 1024; e += 64) {
        int j = e >> 5, i = e & 31;
        out[rowstart + j * 256 + i] = tout[j][i];    // 512B coalesced per warp
        ss [rowstart + j * 256 + i] = tss[j][i];     // 128B coalesced per warp
    }
}

// ---------------- launch ----------------
extern "C" void kernel_launch(void* const* d_in, const int* in_sizes, int n_in,
                              void* d_out, int out_size) {
    (void)in_sizes; (void)n_in; (void)out_size;
    const float2* x = (const float2*)d_in[0];
    float* out = (float*)d_out;                  // (T,4) normalized
    float* ssp = out + 4 * (size_t)T_LEN;        // (T,1) state trace

    k_pre<<<NPRE, 256>>>(x);
    k_refine<1, 0><<<NREF, 128>>>(0, 0);   // init at sigma*, history 256
    k_refine<0, 0><<<NREF, 128>>>(0, 1);   // history 512
    k_refine<0, 1><<<NREF, 128>>>(1, 0);   // stats + 16-step ck + fused finalize
    k_out<<<8 * (B_CH / 32), 64>>>((float4*)out, ssp);
}

// round 14
// speedup vs baseline: 1.4928x; 1.0487x over previous
#include <cuda_runtime.h>
#include <cuda_bf16.h>

// ---------------- constants ----------------
#define T_LEN (1 << 21)          // 2,097,152
#define B_CH  8192               // chains (256 steps each)
#define NPRE  2048               // k_pre blocks
#define NREF  64                 // refine blocks
#define S_EQS (166.0f / 350.0f)  // stationary init in sigma units

// ---------------- device scratch ----------------
// packed quads: 4 consecutive steps of one chain per float4.
// float4 index: ((C>>5)<<11) + ((i>>2)<<5) + (C&31)
__device__ float4 g_d4[(T_LEN / 4) + 1024];  // raw d quads (k_out)
__device__ float4 g_t4[(T_LEN / 4) + 1024];  // ts = tanh(d/350) quads (sweeps)
__device__ float  g_send[2][B_CH];           // ping-pong block end states (sigma)
__device__ float  g_ck[16][B_CH];            // 16-step checkpoints (sigma)
__device__ float  g_prepart[NPRE * 4];       // Σpn, Σpn², Σen, Σen²
__device__ float  g_spart[NREF * 4];         // Σps, Σps², Σpc, Σpc² (rescaled)
__device__ float  g_stats[8];                // mu[4], inv_sigma[4]
__device__ int    g_done;                    // stats-finalize ticket (reset each use)

// ---------------- signed tanh (d-only; off any dependent chain) ----------------
__device__ __forceinline__ float tanh_s(float d) {
    const float INV = 1.0f / 350.0f;
    float m = d * INV;                                  // |m| <= 0.0286
    return m * fmaf(m * m, -0.33333333f, 1.0f);        // odd series, rel err ~9e-8
}

// ---------------- merged sigma-space GR4J step (~15 FMA, 36cy chain) ----------------
// sg in [0,1); ts = tanh(d/350) signed.
template <int OUT>
__device__ __forceinline__ float grs(float sg, float ts, float& ps_o, float& pc_o) {
    constexpr float K9 = 4.0f / 9.0f;
    constexpr float KQ = K9 * K9 * K9 * K9;            // u = KQ * s1^4
    constexpr float A1 = -0.25f * KQ;                  // -(u/4)/v
    constexpr float A2 = 0.15625f * KQ * KQ;           // +(5u^2/32)/v^2
    bool  pos = ts > 0.0f;
    float at  = fabsf(ts);
    float w   = sg * at;                               // sigma*t
    float tmw = at - w;                                // (1-sigma)*t
    float c   = pos ? w : tmw;                         // shared Pade arg
    float omc = 1.0f - c;
    float cc  = c * c;
    float h   = fmaf(cc, omc, omc);                    // 1/(1+c) + O(c^4)
    float g1  = sg * sg;
    float mp  = 1.0f - g1;                             // pos:  1 - sg^2
    float mn  = fmaf(-2.0f, sg, g1);                   // neg:  sg^2 - 2 sg
    float m1  = pos ? mp : mn;
    float z   = m1 * at;
    float s1  = fmaf(z, h, sg);                        // sg + ps  (or sg - es)
    float s1s = s1 * s1;
    float v   = s1s * s1s;                             // s1^4
    float P   = fmaf(v, A2, A1);                       // A1 + A2 v
    float s1v = s1 * v;
    float s2  = fmaf(s1v, P, s1);                      // s1(1 + A1 v + A2 v^2)
    if (OUT) {                                         // off-chain
        ps_o = fmaxf(s1 - sg, 0.0f);                   // ps (0 in neg case)
        pc_o = s1 - s2;                                // perc
    }
    return s2;
}

// ---------------- prologue: d = P-E, packed transpose (d + ts), pn/en stats --------
__global__ void __launch_bounds__(256) k_pre(const float2* __restrict__ x) {
    __shared__ float tile[32][33];
    __shared__ float red[4][256];
    int bid = blockIdx.x;
    int c0  = (bid >> 3) << 5;       // 32-chain group base
    int i0  = (bid & 7) << 5;        // 32-step tile base
    int tid = threadIdx.x;
    float a0 = 0.f, a1 = 0.f, a2 = 0.f, a3 = 0.f;
#pragma unroll
    for (int k = 0; k < 4; k++) {
        int e  = tid + (k << 8);
        int cc = e >> 5, ii = e & 31;
        float2 v = x[(c0 + cc) * 256 + i0 + ii];          // coalesced
        float d  = v.x - v.y;
        float pn = fmaxf(d, 0.0f);
        float en = fmaxf(-d, 0.0f);
        tile[cc][ii] = d;
        a0 += pn; a1 = fmaf(pn, pn, a1);
        a2 += en; a3 = fmaf(en, en, a3);
    }
    __syncthreads();
    {   // packed quad writes: thread -> (chain cc, quad qq)
        int cc = tid & 31, qq = tid >> 5;                 // qq in 0..7
        float d0 = tile[cc][qq * 4 + 0], d1 = tile[cc][qq * 4 + 1];
        float d2 = tile[cc][qq * 4 + 2], d3 = tile[cc][qq * 4 + 3];
        int gi = ((c0 >> 5) << 11) + (((i0 >> 2) + qq) << 5) + cc;
        g_d4[gi] = make_float4(d0, d1, d2, d3);                       // coalesced 512B
        g_t4[gi] = make_float4(tanh_s(d0), tanh_s(d1), tanh_s(d2), tanh_s(d3));
    }
    red[0][tid] = a0; red[1][tid] = a1; red[2][tid] = a2; red[3][tid] = a3;
    __syncthreads();
    for (int o = 128; o > 0; o >>= 1) {
        if (tid < o) {
            red[0][tid] += red[0][tid + o]; red[1][tid] += red[1][tid + o];
            red[2][tid] += red[2][tid + o]; red[3][tid] += red[3][tid + o];
        }
        __syncthreads();
    }
    if (tid < 4) g_prepart[bid * 4 + tid] = red[tid][0];
}

// ---------------- refine pass (STATS: checkpoints + partials + fused finalize) -----
template <int FIRST, int STATS>
__global__ void __launch_bounds__(128) k_refine(int srcIdx, int dstIdx) {
    int C = blockIdx.x * 128 + threadIdx.x;
    const float4* pq = g_t4 + ((C >> 5) << 11) + (C & 31);
    float sg = (C == 0) ? 0.0f : (FIRST ? S_EQS : g_send[srcIdx][C - 1]);
    float q0 = 0.f, q1 = 0.f, q2 = 0.f, q3 = 0.f;
    if (STATS) g_ck[0][C] = sg;
    float4 QA[4], QB[4];
#pragma unroll
    for (int k = 0; k < 4; k++) QA[k] = __ldg(&pq[k << 5]);          // steps 0-15
#pragma unroll
    for (int k = 0; k < 4; k++) QB[k] = __ldg(&pq[(4 + k) << 5]);    // steps 16-31
#pragma unroll 1
    for (int i0 = 0; i0 < 256; i0 += 32) {
        float ts[16];
#pragma unroll
        for (int k = 0; k < 4; k++) {
            ts[4 * k + 0] = QA[k].x; ts[4 * k + 1] = QA[k].y;
            ts[4 * k + 2] = QA[k].z; ts[4 * k + 3] = QA[k].w;
        }
#pragma unroll
        for (int k = 0; k < 4; k++) QA[k] = __ldg(&pq[((i0 >> 2) + 8 + k) << 5]);
#pragma unroll
        for (int j = 0; j < 16; j++) {
            float ps, pc;
            sg = grs<STATS>(sg, ts[j], ps, pc);
            if (STATS) { q0 += ps; q1 = fmaf(ps, ps, q1); q2 += pc; q3 = fmaf(pc, pc, q3); }
        }
        if (STATS) g_ck[(i0 >> 4) + 1][C] = sg;                      // step i0+16
#pragma unroll
        for (int k = 0; k < 4; k++) {
            ts[4 * k + 0] = QB[k].x; ts[4 * k + 1] = QB[k].y;
            ts[4 * k + 2] = QB[k].z; ts[4 * k + 3] = QB[k].w;
        }
#pragma unroll
        for (int k = 0; k < 4; k++) QB[k] = __ldg(&pq[((i0 >> 2) + 12 + k) << 5]);
#pragma unroll
        for (int j = 0; j < 16; j++) {
            float ps, pc;
            sg = grs<STATS>(sg, ts[j], ps, pc);
            if (STATS) { q0 += ps; q1 = fmaf(ps, ps, q1); q2 += pc; q3 = fmaf(pc, pc, q3); }
        }
        if (STATS) {
            int nx = i0 + 32;
            if (nx < 256) g_ck[nx >> 4][C] = sg;                     // step i0+32
        }
    }
    if (!STATS) g_send[dstIdx][C] = sg;
    if (STATS) {
        // rescale sigma-unit sums to physical units once
        q0 *= 350.0f; q1 *= 122500.0f; q2 *= 350.0f; q3 *= 122500.0f;
        __shared__ float rd[4][128];
        __shared__ int lastf;
        int tx = threadIdx.x;
        rd[0][tx] = q0; rd[1][tx] = q1; rd[2][tx] = q2; rd[3][tx] = q3;
        __syncthreads();
        for (int o = 64; o > 0; o >>= 1) {
            if (tx < o) {
                rd[0][tx] += rd[0][tx + o]; rd[1][tx] += rd[1][tx + o];
                rd[2][tx] += rd[2][tx + o]; rd[3][tx] += rd[3][tx + o];
            }
            __syncthreads();
        }
        if (tx < 4) g_spart[blockIdx.x * 4 + tx] = rd[tx][0];
        __threadfence();
        if (tx == 0) lastf = (atomicAdd(&g_done, 1) == NREF - 1);
        __syncthreads();
        if (lastf) {   // last-arriving block finalizes mu / inv_sigma
            __threadfence();
            __shared__ float sd[8][128];
            float acc[8] = {0, 0, 0, 0, 0, 0, 0, 0};
            for (int b = tx; b < NPRE; b += 128) {
                acc[0] += g_prepart[b * 4 + 0]; acc[1] += g_prepart[b * 4 + 1];
                acc[2] += g_prepart[b * 4 + 2]; acc[3] += g_prepart[b * 4 + 3];
            }
            if (tx < NREF) {
                acc[4] = g_spart[tx * 4 + 0]; acc[5] = g_spart[tx * 4 + 1];
                acc[6] = g_spart[tx * 4 + 2]; acc[7] = g_spart[tx * 4 + 3];
            }
#pragma unroll
            for (int k = 0; k < 8; k++) sd[k][tx] = acc[k];
            __syncthreads();
            for (int o = 64; o > 0; o >>= 1) {
                if (tx < o) {
#pragma unroll
                    for (int k = 0; k < 8; k++) sd[k][tx] += sd[k][tx + o];
                }
                __syncthreads();
            }
            if (tx == 0) {
                const float invT = 1.0f / (float)T_LEN;
                float S[4]  = {sd[0][0], sd[2][0], sd[4][0], sd[6][0]};
                float S2[4] = {sd[1][0], sd[3][0], sd[5][0], sd[7][0]};
#pragma unroll
                for (int k = 0; k < 4; k++) {
                    float mu  = S[k] * invT;
                    float var = fmaxf(S2[k] * invT - mu * mu, 0.0f);
                    g_stats[k]     = mu;
                    g_stats[4 + k] = 1.0f / sqrtf(var);
                }
                g_done = 0;     // reset ticket for next graph replay
            }
        }
    }
}

// ---------------- output pass: 16 steps/warp from checkpoints ----------------
__global__ void __launch_bounds__(64) k_out(float4* __restrict__ out, float* __restrict__ ss) {
    __shared__ float4 tout[32][33];
    __shared__ float  tss[32][33];
    int tid  = threadIdx.x;
    int lane = tid & 31;
    int wp   = tid >> 5;             // warp 0/1
    int cg   = blockIdx.x >> 3;      // chain group (32 chains)
    int b    = blockIdx.x & 7;       // 32-step tile index
    int w    = (b << 1) + wp;        // 16-step window index (0..15)
    int C    = (cg << 5) + lane;
    const float4* pq = g_d4 + (cg << 11) + lane;
    float sg = g_ck[w][C];
    // normalization constants (fold 350x rescale for ps/pc/ss)
    float c0 = g_stats[4],          o0 = g_stats[0] * g_stats[4];
    float c1 = g_stats[5],          o1 = g_stats[1] * g_stats[5];
    float c2 = 350.0f * g_stats[6], o2 = g_stats[2] * g_stats[6];
    float c3 = 350.0f * g_stats[7], o3 = g_stats[3] * g_stats[7];
    float4 Qd[4];
#pragma unroll
    for (int k = 0; k < 4; k++) Qd[k] = __ldg(&pq[((w << 2) + k) << 5]);
    int colbase = wp << 4;           // this warp's 16 columns within the 32-step tile
#pragma unroll
    for (int q = 0; q < 4; q++) {
        float dv[4] = {Qd[q].x, Qd[q].y, Qd[q].z, Qd[q].w};
#pragma unroll
        for (int j = 0; j < 4; j++) {
            float d  = dv[j];
            float pn = fmaxf(d, 0.0f);
            float en = fmaxf(-d, 0.0f);
            float ps, pc;
            sg = grs<1>(sg, tanh_s(d), ps, pc);     // bit-identical ts to stored one
            tout[lane][colbase + q * 4 + j] = make_float4(fmaf(pn, c0, -o0),
                                                          fmaf(en, c1, -o1),
                                                          fmaf(ps, c2, -o2),
                                                          fmaf(pc, c3, -o3));
            tss[lane][colbase + q * 4 + j] = 350.0f * sg;
        }
    }
    __syncthreads();
    int rowstart = (cg << 13) + (b << 5);
#pragma unroll 1
    for (int e = tid; e < 1024; e += 64) {
        int j = e >> 5, i = e & 31;
        out[rowstart + j * 256 + i] = tout[j][i];    // 512B coalesced per warp
        ss [rowstart + j * 256 + i] = tss[j][i];     // 128B coalesced per warp
    }
}

// ---------------- launch ----------------
extern "C" void kernel_launch(void* const* d_in, const int* in_sizes, int n_in,
                              void* d_out, int out_size) {
    (void)in_sizes; (void)n_in; (void)out_size;
    const float2* x = (const float2*)d_in[0];
    float* out = (float*)d_out;                  // (T,4) normalized
    float* ssp = out + 4 * (size_t)T_LEN;        // (T,1) state trace

    k_pre<<<NPRE, 256>>>(x);
    k_refine<1, 0><<<NREF, 128>>>(0, 0);   // init at sigma*, history 256
    k_refine<0, 0><<<NREF, 128>>>(0, 1);   // history 512
    k_refine<0, 1><<<NREF, 128>>>(1, 0);   // stats + 16-step ck + fused finalize
    k_out<<<8 * (B_CH / 32), 64>>>((float4*)out, ssp);
}

// round 15
// speedup vs baseline: 1.5330x; 1.0269x over previous
#include <cuda_runtime.h>
#include <cuda_bf16.h>

// ---------------- constants ----------------
#define T_LEN (1 << 21)          // 2,097,152
#define B_CH  8192               // chains (256 steps each)
#define NPRE  2048               // k_pre blocks
#define NREF  64                 // refine blocks
#define S_EQS (166.0f / 350.0f)  // stationary init in sigma units

// ---------------- device scratch ----------------
// packed quads: 4 consecutive steps of one chain per float4.
// float4 index: ((C>>5)<<11) + ((i>>2)<<5) + (C&31)
__device__ float4 g_t4[(T_LEN / 4) + 1024];  // ts = tanh(d/350) quads (ALL passes)
__device__ float  g_send[2][B_CH];           // ping-pong block end states (sigma)
__device__ float  g_ck[16][B_CH];            // 16-step checkpoints (sigma)
__device__ float  g_prepart[NPRE * 4];       // Σpn, Σpn², Σen, Σen²
__device__ float  g_spart[NREF * 4];         // Σps, Σps², Σpc, Σpc² (rescaled)
__device__ float  g_stats[8];                // mu[4], inv_sigma[4]
__device__ int    g_done;                    // stats-finalize ticket (reset each use)

// ---------------- signed tanh (d-only) ----------------
__device__ __forceinline__ float tanh_s(float d) {
    const float INV = 1.0f / 350.0f;
    float m = d * INV;                                  // |m| <= 0.0286
    return m * fmaf(m * m, -0.33333333f, 1.0f);        // odd series, rel err ~9e-8
}

// ---------------- affine-coefficient sigma-space GR4J step (32cy chain) -----------
// c = ts*sg + alpha,  z = G + sg*(D + E*sg),  s1 = sg + z*h,  h = 1/(1+c).
// alpha=max(-ts,0), G=max(ts,0), D=min(2ts,0), E=-ts  (all ts-only, off-chain).
template <int OUT>
__device__ __forceinline__ float grs(float sg, float ts, float& ps_o, float& pc_o) {
    constexpr float K9 = 4.0f / 9.0f;
    constexpr float KQ = K9 * K9 * K9 * K9;            // u = KQ * s1^4
    constexpr float A1 = -0.25f * KQ;
    constexpr float A2 = 0.15625f * KQ * KQ;
    float alpha = fmaxf(-ts, 0.0f);                    // ALU, off-chain
    float G     = fmaxf(ts, 0.0f);                     // ALU, off-chain
    float D     = fminf(ts + ts, 0.0f);                // off-chain
    float c     = fmaf(ts, sg, alpha);                 // sg+4
    float omc   = 1.0f - c;                            // sg+8
    float cc    = c * c;                               // sg+8
    float h     = fmaf(cc, omc, omc);                  // sg+12 : 1/(1+c)+O(c^4)
    float inner = fmaf(-ts, sg, D);                    // sg+4
    float z     = fmaf(sg, inner, G);                  // sg+8
    float s1    = fmaf(z, h, sg);                      // sg+16
    float s1s   = s1 * s1;
    float v     = s1s * s1s;                           // s1^4
    float P     = fmaf(v, A2, A1);
    float s1v   = s1 * v;
    float s2    = fmaf(s1v, P, s1);                    // s1+16
    if (OUT) {                                         // off-chain
        ps_o = fmaxf(s1 - sg, 0.0f);                   // ps (0 in neg case)
        pc_o = s1 - s2;                                // perc
    }
    return s2;
}

// ---------------- prologue: d = P-E, ts quads (packed transpose), pn/en stats -----
__global__ void __launch_bounds__(256) k_pre(const float2* __restrict__ x) {
    __shared__ float tile[32][33];
    __shared__ float red[4][256];
    int bid = blockIdx.x;
    int c0  = (bid >> 3) << 5;       // 32-chain group base
    int i0  = (bid & 7) << 5;        // 32-step tile base
    int tid = threadIdx.x;
    float a0 = 0.f, a1 = 0.f, a2 = 0.f, a3 = 0.f;
#pragma unroll
    for (int k = 0; k < 4; k++) {
        int e  = tid + (k << 8);
        int cc = e >> 5, ii = e & 31;
        float2 v = x[(c0 + cc) * 256 + i0 + ii];          // coalesced
        float d  = v.x - v.y;
        float pn = fmaxf(d, 0.0f);
        float en = fmaxf(-d, 0.0f);
        tile[cc][ii] = tanh_s(d);
        a0 += pn; a1 = fmaf(pn, pn, a1);
        a2 += en; a3 = fmaf(en, en, a3);
    }
    __syncthreads();
    {   // packed quad write: thread -> (chain cc, quad qq)
        int cc = tid & 31, qq = tid >> 5;                 // qq in 0..7
        float4 v4 = make_float4(tile[cc][qq * 4 + 0], tile[cc][qq * 4 + 1],
                                tile[cc][qq * 4 + 2], tile[cc][qq * 4 + 3]);
        g_t4[((c0 >> 5) << 11) + (((i0 >> 2) + qq) << 5) + cc] = v4;  // coalesced 512B
    }
    red[0][tid] = a0; red[1][tid] = a1; red[2][tid] = a2; red[3][tid] = a3;
    __syncthreads();
    for (int o = 128; o > 0; o >>= 1) {
        if (tid < o) {
            red[0][tid] += red[0][tid + o]; red[1][tid] += red[1][tid + o];
            red[2][tid] += red[2][tid + o]; red[3][tid] += red[3][tid + o];
        }
        __syncthreads();
    }
    if (tid < 4) g_prepart[bid * 4 + tid] = red[tid][0];
}

// ---------------- refine pass (STATS: checkpoints + partials + fused finalize) -----
template <int FIRST, int STATS>
__global__ void __launch_bounds__(128) k_refine(int srcIdx, int dstIdx) {
    int C = blockIdx.x * 128 + threadIdx.x;
    const float4* pq = g_t4 + ((C >> 5) << 11) + (C & 31);
    float sg = (C == 0) ? 0.0f : (FIRST ? S_EQS : g_send[srcIdx][C - 1]);
    float q0 = 0.f, q1 = 0.f, q2 = 0.f, q3 = 0.f;
    if (STATS) g_ck[0][C] = sg;
    float4 QA[4], QB[4];
#pragma unroll
    for (int k = 0; k < 4; k++) QA[k] = __ldg(&pq[k << 5]);          // steps 0-15
#pragma unroll
    for (int k = 0; k < 4; k++) QB[k] = __ldg(&pq[(4 + k) << 5]);    // steps 16-31
#pragma unroll 1
    for (int i0 = 0; i0 < 256; i0 += 32) {
        float ts[16];
#pragma unroll
        for (int k = 0; k < 4; k++) {
            ts[4 * k + 0] = QA[k].x; ts[4 * k + 1] = QA[k].y;
            ts[4 * k + 2] = QA[k].z; ts[4 * k + 3] = QA[k].w;
        }
#pragma unroll
        for (int k = 0; k < 4; k++) QA[k] = __ldg(&pq[((i0 >> 2) + 8 + k) << 5]);
#pragma unroll
        for (int j = 0; j < 16; j++) {
            float ps, pc;
            sg = grs<STATS>(sg, ts[j], ps, pc);
            if (STATS) { q0 += ps; q1 = fmaf(ps, ps, q1); q2 += pc; q3 = fmaf(pc, pc, q3); }
        }
        if (STATS) g_ck[(i0 >> 4) + 1][C] = sg;                      // step i0+16
#pragma unroll
        for (int k = 0; k < 4; k++) {
            ts[4 * k + 0] = QB[k].x; ts[4 * k + 1] = QB[k].y;
            ts[4 * k + 2] = QB[k].z; ts[4 * k + 3] = QB[k].w;
        }
#pragma unroll
        for (int k = 0; k < 4; k++) QB[k] = __ldg(&pq[((i0 >> 2) + 12 + k) << 5]);
#pragma unroll
        for (int j = 0; j < 16; j++) {
            float ps, pc;
            sg = grs<STATS>(sg, ts[j], ps, pc);
            if (STATS) { q0 += ps; q1 = fmaf(ps, ps, q1); q2 += pc; q3 = fmaf(pc, pc, q3); }
        }
        if (STATS) {
            int nx = i0 + 32;
            if (nx < 256) g_ck[nx >> 4][C] = sg;                     // step i0+32
        }
    }
    if (!STATS) g_send[dstIdx][C] = sg;
    if (STATS) {
        // rescale sigma-unit sums to physical units once
        q0 *= 350.0f; q1 *= 122500.0f; q2 *= 350.0f; q3 *= 122500.0f;
        __shared__ float rd[4][128];
        __shared__ int lastf;
        int tx = threadIdx.x;
        rd[0][tx] = q0; rd[1][tx] = q1; rd[2][tx] = q2; rd[3][tx] = q3;
        __syncthreads();
        for (int o = 64; o > 0; o >>= 1) {
            if (tx < o) {
                rd[0][tx] += rd[0][tx + o]; rd[1][tx] += rd[1][tx + o];
                rd[2][tx] += rd[2][tx + o]; rd[3][tx] += rd[3][tx + o];
            }
            __syncthreads();
        }
        if (tx < 4) g_spart[blockIdx.x * 4 + tx] = rd[tx][0];
        __threadfence();
        if (tx == 0) lastf = (atomicAdd(&g_done, 1) == NREF - 1);
        __syncthreads();
        if (lastf) {   // last-arriving block finalizes mu / inv_sigma
            __threadfence();
            __shared__ float sd[8][128];
            float acc[8] = {0, 0, 0, 0, 0, 0, 0, 0};
            for (int b = tx; b < NPRE; b += 128) {
                acc[0] += g_prepart[b * 4 + 0]; acc[1] += g_prepart[b * 4 + 1];
                acc[2] += g_prepart[b * 4 + 2]; acc[3] += g_prepart[b * 4 + 3];
            }
            if (tx < NREF) {
                acc[4] = g_spart[tx * 4 + 0]; acc[5] = g_spart[tx * 4 + 1];
                acc[6] = g_spart[tx * 4 + 2]; acc[7] = g_spart[tx * 4 + 3];
            }
#pragma unroll
            for (int k = 0; k < 8; k++) sd[k][tx] = acc[k];
            __syncthreads();
            for (int o = 64; o > 0; o >>= 1) {
                if (tx < o) {
#pragma unroll
                    for (int k = 0; k < 8; k++) sd[k][tx] += sd[k][tx + o];
                }
                __syncthreads();
            }
            if (tx == 0) {
                const float invT = 1.0f / (float)T_LEN;
                float S[4]  = {sd[0][0], sd[2][0], sd[4][0], sd[6][0]};
                float S2[4] = {sd[1][0], sd[3][0], sd[5][0], sd[7][0]};
#pragma unroll
                for (int k = 0; k < 4; k++) {
                    float mu  = S[k] * invT;
                    float var = fmaxf(S2[k] * invT - mu * mu, 0.0f);
                    g_stats[k]     = mu;
                    g_stats[4 + k] = 1.0f / sqrtf(var);
                }
                g_done = 0;     // reset ticket for next graph replay
            }
        }
    }
}

// ---------------- output pass: 16 steps/warp from checkpoints ----------------
__global__ void __launch_bounds__(64) k_out(float4* __restrict__ out, float* __restrict__ ss) {
    __shared__ float4 tout[32][33];
    __shared__ float  tss[32][33];
    int tid  = threadIdx.x;
    int lane = tid & 31;
    int wp   = tid >> 5;             // warp 0/1
    int cg   = blockIdx.x >> 3;      // chain group (32 chains)
    int b    = blockIdx.x & 7;       // 32-step tile index
    int w    = (b << 1) + wp;        // 16-step window index (0..15)
    int C    = (cg << 5) + lane;
    const float4* pq = g_t4 + (cg << 11) + lane;
    float sg = g_ck[w][C];
    // normalization constants: pn/en carry 350x (reconstructed m units), ps/pc/ss too
    float c0 = 350.0f * g_stats[4], o0 = g_stats[0] * g_stats[4];
    float c1 = 350.0f * g_stats[5], o1 = g_stats[1] * g_stats[5];
    float c2 = 350.0f * g_stats[6], o2 = g_stats[2] * g_stats[6];
    float c3 = 350.0f * g_stats[7], o3 = g_stats[3] * g_stats[7];
    float4 Qt[4];
#pragma unroll
    for (int k = 0; k < 4; k++) Qt[k] = __ldg(&pq[((w << 2) + k) << 5]);
    int colbase = wp << 4;           // this warp's 16 columns within the 32-step tile
#pragma unroll
    for (int q = 0; q < 4; q++) {
        float tv[4] = {Qt[q].x, Qt[q].y, Qt[q].z, Qt[q].w};
#pragma unroll
        for (int j = 0; j < 4; j++) {
            float ts = tv[j];
            // invert tanh series: m = ts + ts^3/3  (rel err ~2e-7);  pn/en = 350*max(+/-m,0)
            float t2 = ts * ts;
            float m  = fmaf(t2 * ts, 0.33333333f, ts);
            float pn = fmaxf(m, 0.0f);
            float en = fmaxf(-m, 0.0f);
            float ps, pc;
            sg = grs<1>(sg, ts, ps, pc);
            tout[lane][colbase + q * 4 + j] = make_float4(fmaf(pn, c0, -o0),
                                                          fmaf(en, c1, -o1),
                                                          fmaf(ps, c2, -o2),
                                                          fmaf(pc, c3, -o3));
            tss[lane][colbase + q * 4 + j] = 350.0f * sg;
        }
    }
    __syncthreads();
    int rowstart = (cg << 13) + (b << 5);
#pragma unroll 1
    for (int e = tid; e < 1024; e += 64) {
        int j = e >> 5, i = e & 31;
        out[rowstart + j * 256 + i] = tout[j][i];    // 512B coalesced per warp
        ss [rowstart + j * 256 + i] = tss[j][i];     // 128B coalesced per warp
    }
}

// ---------------- launch ----------------
extern "C" void kernel_launch(void* const* d_in, const int* in_sizes, int n_in,
                              void* d_out, int out_size) {
    (void)in_sizes; (void)n_in; (void)out_size;
    const float2* x = (const float2*)d_in[0];
    float* out = (float*)d_out;                  // (T,4) normalized
    float* ssp = out + 4 * (size_t)T_LEN;        // (T,1) state trace

    k_pre<<<NPRE, 256>>>(x);
    k_refine<1, 0><<<NREF, 128>>>(0, 0);   // init at sigma*, history 256
    k_refine<0, 0><<<NREF, 128>>>(0, 1);   // history 512
    k_refine<0, 1><<<NREF, 128>>>(1, 0);   // stats + 16-step ck + fused finalize
    k_out<<<8 * (B_CH / 32), 64>>>((float4*)out, ssp);
}